// round 1
// baseline (speedup 1.0000x reference)
#include <cuda_runtime.h>
#include <cuda_bf16.h>
#include <math.h>

#define NN 50000
#define EE 600000
#define FIN 500
#define HH 64
#define CC 40

// ---------------- scratch (static __device__ globals, allowed) ----------------
__device__ float g_x0 [NN*HH];   // encoder output == x0 (first half)
__device__ float g_buf0[NN*HH];  // z
__device__ float g_buf1[NN*HH];  // ua
__device__ float g_buf2[NN*HH];  // ub
__device__ float g_acc [NN*HH];  // RK accumulator
__device__ float g_s   [NN];     // 0.5 * sigmoid(alpha)
__device__ int   g_rowptr[NN+1];
__device__ int   g_cnt [NN];     // histogram, then scatter cursor
__device__ int   g_col [EE];
__device__ float g_wv  [EE];
__device__ int   g_bsums[64];

__device__ __forceinline__ float* pick_buf(int id) {
    return id == 0 ? g_buf0 : (id == 1 ? g_buf1 : g_buf2);
}

// ---------------- encoder GEMM: h = x @ m1_w + m1_b -> g_x0, g_buf0 -----------
// BM=128, BN=64, BK=20 (500 = 25*20, no K remainder)
#define BM 128
#define BN 64
#define BK 20
__global__ __launch_bounds__(256) void encoder_gemm(
    const float* __restrict__ X, const float* __restrict__ W,
    const float* __restrict__ bias)
{
    __shared__ float As[BK][BM+1];   // +1 pad: conflict-free strided stores
    __shared__ float Bs[BK][BN];
    const int bm = blockIdx.x * BM;
    const int t  = threadIdx.x;           // 0..255
    const int tx = t & 15;                // col group (4 cols)
    const int ty = t >> 4;                // row group (8 rows)
    float acc[8][4];
    #pragma unroll
    for (int i = 0; i < 8; i++)
        #pragma unroll
        for (int j = 0; j < 4; j++) acc[i][j] = 0.f;

    for (int k0 = 0; k0 < FIN; k0 += BK) {
        #pragma unroll
        for (int i = 0; i < 10; i++) {            // 2560 A elems / 256 thr
            int idx = t + i * 256;
            int m  = idx / BK;
            int kk = idx % BK;
            int gr = bm + m;
            As[kk][m] = (gr < NN) ? X[gr * FIN + k0 + kk] : 0.f;
        }
        #pragma unroll
        for (int i = 0; i < 5; i++) {             // 1280 B elems / 256 thr
            int idx = t + i * 256;
            int kk = idx / BN, n = idx % BN;
            Bs[kk][n] = W[(k0 + kk) * HH + n];
        }
        __syncthreads();
        #pragma unroll
        for (int kk = 0; kk < BK; kk++) {
            float a[8];
            #pragma unroll
            for (int i = 0; i < 8; i++) a[i] = As[kk][ty * 8 + i];
            float4 b4 = *(const float4*)&Bs[kk][tx * 4];
            float b[4] = {b4.x, b4.y, b4.z, b4.w};
            #pragma unroll
            for (int i = 0; i < 8; i++)
                #pragma unroll
                for (int j = 0; j < 4; j++) acc[i][j] = fmaf(a[i], b[j], acc[i][j]);
        }
        __syncthreads();
    }
    #pragma unroll
    for (int i = 0; i < 8; i++) {
        int gr = bm + ty * 8 + i;
        if (gr < NN) {
            #pragma unroll
            for (int j = 0; j < 4; j++) {
                int gc = tx * 4 + j;
                float v = acc[i][j] + bias[gc];
                g_x0  [gr * HH + gc] = v;
                g_buf0[gr * HH + gc] = v;
            }
        }
    }
}

// ---------------- misc small kernels ----------------
__global__ void sigmoid_kernel(const float* __restrict__ a) {
    int i = blockIdx.x * blockDim.x + threadIdx.x;
    if (i < NN) g_s[i] = 0.5f / (1.f + __expf(-a[i]));
}

__global__ void zero_cnt_kernel() {
    int i = blockIdx.x * blockDim.x + threadIdx.x;
    if (i < NN) g_cnt[i] = 0;
}

__global__ void hist_kernel(const int* __restrict__ src) {
    int e = blockIdx.x * blockDim.x + threadIdx.x;
    if (e < EE) atomicAdd(&g_cnt[src[e]], 1);
}

__global__ void scan_block_kernel() {   // grid 49, block 1024
    __shared__ int sh[1024];
    int i = blockIdx.x * 1024 + threadIdx.x;
    int v = (i < NN) ? g_cnt[i] : 0;
    sh[threadIdx.x] = v;
    __syncthreads();
    for (int off = 1; off < 1024; off <<= 1) {
        int tmp = 0;
        if ((int)threadIdx.x >= off) tmp = sh[threadIdx.x - off];
        __syncthreads();
        sh[threadIdx.x] += tmp;
        __syncthreads();
    }
    if (i < NN) g_rowptr[i] = sh[threadIdx.x] - v;   // exclusive within block
    if (threadIdx.x == 1023) g_bsums[blockIdx.x] = sh[1023];
}

__global__ void scan_tops_kernel(int nb) {   // 1 block
    if (threadIdx.x == 0) {
        int run = 0;
        for (int b = 0; b < nb; b++) { int t = g_bsums[b]; g_bsums[b] = run; run += t; }
    }
}

__global__ void scan_add_kernel() {
    int i = blockIdx.x * 1024 + threadIdx.x;
    if (i < NN) {
        int v = g_rowptr[i] + g_bsums[blockIdx.x];
        g_rowptr[i] = v;
        g_cnt[i] = v;           // cursor for scatter
    }
    if (i == 0) g_rowptr[NN] = EE;
}

__global__ void scatter_kernel(const int* __restrict__ src, const int* __restrict__ dst,
                               const float* __restrict__ w) {
    int e = blockIdx.x * blockDim.x + threadIdx.x;
    if (e < EE) {
        int s = src[e];
        int p = atomicAdd(&g_cnt[s], 1);
        g_col[p] = dst[e];
        g_wv [p] = w[e];
    }
}

// ---------------- fused RK4 stage: warp per node -----------------------------
// MODE 0 (stage1): acc = z + cA*k ; un = z + cN*k
// MODE 1 (stg2,3): acc += cA*k    ; un = z + cN*k
// MODE 2 (stage4): z(=un) = acc + cA*k
template<int MODE>
__global__ __launch_bounds__(256) void stage_kernel(int uid, int unid, float cA, float cN)
{
    int wid = (blockIdx.x * blockDim.x + threadIdx.x) >> 5;
    if (wid >= NN) return;
    const int lane = threadIdx.x & 31;
    const float2* __restrict__ u2 = reinterpret_cast<const float2*>(pick_buf(uid));
    const int rbase = wid * 32 + lane;

    const int beg = g_rowptr[wid];
    const int end = g_rowptr[wid + 1];
    float ax = 0.f, ay = 0.f;
    int e = beg;
    for (; e + 4 <= end; e += 4) {
        int   j0 = g_col[e+0], j1 = g_col[e+1], j2 = g_col[e+2], j3 = g_col[e+3];
        float w0 = g_wv [e+0], w1 = g_wv [e+1], w2 = g_wv [e+2], w3 = g_wv [e+3];
        float2 v0 = u2[j0*32+lane], v1 = u2[j1*32+lane];
        float2 v2 = u2[j2*32+lane], v3 = u2[j3*32+lane];
        ax = fmaf(w0, v0.x, ax); ay = fmaf(w0, v0.y, ay);
        ax = fmaf(w1, v1.x, ax); ay = fmaf(w1, v1.y, ay);
        ax = fmaf(w2, v2.x, ax); ay = fmaf(w2, v2.y, ay);
        ax = fmaf(w3, v3.x, ax); ay = fmaf(w3, v3.y, ay);
    }
    for (; e < end; e++) {
        int j = g_col[e]; float w = g_wv[e];
        float2 v = u2[j*32+lane];
        ax = fmaf(w, v.x, ax); ay = fmaf(w, v.y, ay);
    }

    float2 ui  = u2[rbase];
    float2 x0v = reinterpret_cast<const float2*>(g_x0)[rbase];
    float  s   = g_s[wid];
    float  kx  = fmaf(s, ax - ui.x, x0v.x);
    float  ky  = fmaf(s, ay - ui.y, x0v.y);

    float2* acc2 = reinterpret_cast<float2*>(g_acc);
    float2* un2  = reinterpret_cast<float2*>(pick_buf(unid));
    if (MODE == 0) {
        float2 zv = reinterpret_cast<const float2*>(g_buf0)[rbase];
        acc2[rbase] = make_float2(fmaf(cA, kx, zv.x), fmaf(cA, ky, zv.y));
        un2 [rbase] = make_float2(fmaf(cN, kx, zv.x), fmaf(cN, ky, zv.y));
    } else if (MODE == 1) {
        float2 av = acc2[rbase];
        acc2[rbase] = make_float2(fmaf(cA, kx, av.x), fmaf(cA, ky, av.y));
        float2 zv = reinterpret_cast<const float2*>(g_buf0)[rbase];
        un2 [rbase] = make_float2(fmaf(cN, kx, zv.x), fmaf(cN, ky, zv.y));
    } else {
        float2 av = acc2[rbase];
        un2 [rbase] = make_float2(fmaf(cA, kx, av.x), fmaf(cA, ky, av.y));
    }
}

// ---------------- classifier: out = relu(z) @ m2_w + m2_b --------------------
__global__ __launch_bounds__(256) void classifier_kernel(
    const float* __restrict__ W, const float* __restrict__ bias,
    float* __restrict__ out)
{
    __shared__ float ws[HH * CC];
    __shared__ float bs[CC];
    const int t = threadIdx.x;
    #pragma unroll
    for (int i = 0; i < 10; i++) ws[t + i * 256] = W[t + i * 256];
    if (t < CC) bs[t] = bias[t];
    __syncthreads();
    int gid = blockIdx.x * 256 + t;
    if (gid >= NN * CC) return;
    int node = gid / CC, c = gid % CC;
    const float* zr = g_buf0 + node * HH;
    float acc = bs[c];
    #pragma unroll
    for (int k = 0; k < HH; k++) {
        float zv = fmaxf(__ldg(zr + k), 0.f);
        acc = fmaf(zv, ws[k * CC + c], acc);
    }
    out[gid] = acc;
}

// ---------------- launch ----------------
extern "C" void kernel_launch(void* const* d_in, const int* in_sizes, int n_in,
                              void* d_out, int out_size)
{
    const float* x    = (const float*)d_in[0];
    const float* ew   = (const float*)d_in[1];
    const float* m1w  = (const float*)d_in[2];
    const float* m1b  = (const float*)d_in[3];
    const float* alph = (const float*)d_in[4];
    const float* m2w  = (const float*)d_in[5];
    const float* m2b  = (const float*)d_in[6];
    const int*   esrc = (const int*)d_in[7];
    const int*   edst = (const int*)d_in[8];
    float* out = (float*)d_out;

    const float dt = 1.0f / 4.0f;

    // encoder + sigmoid
    encoder_gemm<<<(NN + BM - 1) / BM, 256>>>(x, m1w, m1b);
    sigmoid_kernel<<<(NN + 255) / 256, 256>>>(alph);

    // CSR build (counting sort by src)
    zero_cnt_kernel<<<(NN + 255) / 256, 256>>>();
    hist_kernel<<<(EE + 255) / 256, 256>>>(esrc);
    const int nb = (NN + 1023) / 1024;
    scan_block_kernel<<<nb, 1024>>>();
    scan_tops_kernel<<<1, 32>>>(nb);
    scan_add_kernel<<<nb, 1024>>>();
    scatter_kernel<<<(EE + 255) / 256, 256>>>(esrc, edst, ew);

    // RK4: 4 steps x 4 stages (warp per node)
    const int sgrid = (NN * 32 + 255) / 256;
    for (int step = 0; step < 4; step++) {
        stage_kernel<0><<<sgrid, 256>>>(0, 1, dt / 6.f, dt * 0.5f);
        stage_kernel<1><<<sgrid, 256>>>(1, 2, dt / 3.f, dt * 0.5f);
        stage_kernel<1><<<sgrid, 256>>>(2, 1, dt / 3.f, dt);
        stage_kernel<2><<<sgrid, 256>>>(1, 0, dt / 6.f, 0.f);
    }

    // classifier
    classifier_kernel<<<(NN * CC + 255) / 256, 256>>>(m2w, m2b, out);
}

// round 2
// speedup vs baseline: 1.0079x; 1.0079x over previous
#include <cuda_runtime.h>
#include <cuda_bf16.h>
#include <cuda_fp16.h>
#include <math.h>

#define NN 50000
#define EE 600000
#define FIN 500
#define HH 64
#define CC 40

// ---------------- scratch (static __device__ globals, allowed) ----------------
__device__ float  g_x0 [NN*HH];   // encoder output == x0 (fp32)
__device__ float  g_buf0[NN*HH];  // z master copy (fp32)
__device__ float  g_acc [NN*HH];  // RK accumulator (fp32)
__device__ __half g_zh [NN*HH];   // fp16 shadow of z (gather operand, stage 1)
__device__ __half g_u1h[NN*HH];   // fp16 stage state
__device__ __half g_u2h[NN*HH];   // fp16 stage state
__device__ float  g_s   [NN];     // 0.5 * sigmoid(alpha)
__device__ int    g_rowptr[NN+1];
__device__ int    g_cnt [NN];     // histogram, then scatter cursor
__device__ int    g_col [EE];
__device__ float  g_wv  [EE];
__device__ int    g_bsums[64];

__device__ __forceinline__ __half2* pick_h(int id) {
    return reinterpret_cast<__half2*>(id == 0 ? g_zh : (id == 1 ? g_u1h : g_u2h));
}

// ---------------- encoder GEMM: h = x @ m1_w + m1_b -> g_x0, g_buf0, g_zh -----
// BM=128, BN=64, BK=20 (500 = 25*20, no K remainder)
#define BM 128
#define BN 64
#define BK 20
__global__ __launch_bounds__(256) void encoder_gemm(
    const float* __restrict__ X, const float* __restrict__ W,
    const float* __restrict__ bias)
{
    __shared__ float As[BK][BM+1];
    __shared__ float Bs[BK][BN];
    const int bm = blockIdx.x * BM;
    const int t  = threadIdx.x;           // 0..255
    const int tx = t & 15;                // col group (4 cols)
    const int ty = t >> 4;                // row group (8 rows)
    float acc[8][4];
    #pragma unroll
    for (int i = 0; i < 8; i++)
        #pragma unroll
        for (int j = 0; j < 4; j++) acc[i][j] = 0.f;

    for (int k0 = 0; k0 < FIN; k0 += BK) {
        #pragma unroll
        for (int i = 0; i < 10; i++) {            // 2560 A elems / 256 thr
            int idx = t + i * 256;
            int m  = idx / BK;
            int kk = idx % BK;
            int gr = bm + m;
            As[kk][m] = (gr < NN) ? X[gr * FIN + k0 + kk] : 0.f;
        }
        #pragma unroll
        for (int i = 0; i < 5; i++) {             // 1280 B elems / 256 thr
            int idx = t + i * 256;
            int kk = idx / BN, n = idx % BN;
            Bs[kk][n] = W[(k0 + kk) * HH + n];
        }
        __syncthreads();
        #pragma unroll
        for (int kk = 0; kk < BK; kk++) {
            float a[8];
            #pragma unroll
            for (int i = 0; i < 8; i++) a[i] = As[kk][ty * 8 + i];
            float4 b4 = *(const float4*)&Bs[kk][tx * 4];
            float b[4] = {b4.x, b4.y, b4.z, b4.w};
            #pragma unroll
            for (int i = 0; i < 8; i++)
                #pragma unroll
                for (int j = 0; j < 4; j++) acc[i][j] = fmaf(a[i], b[j], acc[i][j]);
        }
        __syncthreads();
    }
    __half2* zh2 = reinterpret_cast<__half2*>(g_zh);
    #pragma unroll
    for (int i = 0; i < 8; i++) {
        int gr = bm + ty * 8 + i;
        if (gr < NN) {
            #pragma unroll
            for (int j = 0; j < 4; j += 2) {
                int gc = tx * 4 + j;
                float v0 = acc[i][j]   + bias[gc];
                float v1 = acc[i][j+1] + bias[gc+1];
                g_x0  [gr * HH + gc]     = v0;
                g_x0  [gr * HH + gc + 1] = v1;
                g_buf0[gr * HH + gc]     = v0;
                g_buf0[gr * HH + gc + 1] = v1;
                zh2[(gr * HH + gc) >> 1] = __floats2half2_rn(v0, v1);
            }
        }
    }
}

// ---------------- fused sigmoid + counter zero ----------------
__global__ void sigmoid_zero_kernel(const float* __restrict__ a) {
    int i = blockIdx.x * blockDim.x + threadIdx.x;
    if (i < NN) {
        g_s[i]   = 0.5f / (1.f + __expf(-a[i]));
        g_cnt[i] = 0;
    }
}

__global__ void hist_kernel(const int* __restrict__ src) {
    int e = blockIdx.x * blockDim.x + threadIdx.x;
    if (e < EE) atomicAdd(&g_cnt[src[e]], 1);
}

__global__ void scan_block_kernel() {   // grid 49, block 1024
    __shared__ int sh[1024];
    int i = blockIdx.x * 1024 + threadIdx.x;
    int v = (i < NN) ? g_cnt[i] : 0;
    sh[threadIdx.x] = v;
    __syncthreads();
    for (int off = 1; off < 1024; off <<= 1) {
        int tmp = 0;
        if ((int)threadIdx.x >= off) tmp = sh[threadIdx.x - off];
        __syncthreads();
        sh[threadIdx.x] += tmp;
        __syncthreads();
    }
    if (i < NN) g_rowptr[i] = sh[threadIdx.x] - v;   // exclusive within block
    if (threadIdx.x == 1023) g_bsums[blockIdx.x] = sh[1023];
}

__global__ void scan_tops_kernel(int nb) {   // 1 block
    if (threadIdx.x == 0) {
        int run = 0;
        for (int b = 0; b < nb; b++) { int t = g_bsums[b]; g_bsums[b] = run; run += t; }
    }
}

__global__ void scan_add_kernel() {
    int i = blockIdx.x * 1024 + threadIdx.x;
    if (i < NN) {
        int v = g_rowptr[i] + g_bsums[blockIdx.x];
        g_rowptr[i] = v;
        g_cnt[i] = v;           // cursor for scatter
    }
    if (i == 0) g_rowptr[NN] = EE;
}

__global__ void scatter_kernel(const int* __restrict__ src, const int* __restrict__ dst,
                               const float* __restrict__ w) {
    int e = blockIdx.x * blockDim.x + threadIdx.x;
    if (e < EE) {
        int s = src[e];
        int p = atomicAdd(&g_cnt[s], 1);
        g_col[p] = dst[e];
        g_wv [p] = w[e];
    }
}

// ---------------- fused RK4 stage: warp per node, fp16 gather ----------------
// Gather operand ug (fp16), output state unh (fp16). fp32 master z/acc/x0.
// MODE 0 (stage1): own u = z (fp32);  acc = z + cA*k ; un = z + cN*k
// MODE 1 (stg2,3): own u = ug (fp16); acc += cA*k    ; un = z + cN*k
// MODE 2 (stage4): own u = ug (fp16); z = acc + cA*k  (write fp32 z + fp16 zh)
template<int MODE>
__global__ __launch_bounds__(256) void stage_kernel(int ugid, int unid, float cA, float cN)
{
    int wid = (blockIdx.x * blockDim.x + threadIdx.x) >> 5;
    if (wid >= NN) return;
    const int lane = threadIdx.x & 31;
    const __half2* __restrict__ ug = pick_h(ugid);
    const int rbase = wid * 32 + lane;

    const int beg = g_rowptr[wid];
    const int end = g_rowptr[wid + 1];
    float ax = 0.f, ay = 0.f;
    int e = beg;
    for (; e + 4 <= end; e += 4) {
        int   j0 = g_col[e+0], j1 = g_col[e+1], j2 = g_col[e+2], j3 = g_col[e+3];
        float w0 = g_wv [e+0], w1 = g_wv [e+1], w2 = g_wv [e+2], w3 = g_wv [e+3];
        float2 v0 = __half22float2(ug[j0*32+lane]);
        float2 v1 = __half22float2(ug[j1*32+lane]);
        float2 v2 = __half22float2(ug[j2*32+lane]);
        float2 v3 = __half22float2(ug[j3*32+lane]);
        ax = fmaf(w0, v0.x, ax); ay = fmaf(w0, v0.y, ay);
        ax = fmaf(w1, v1.x, ax); ay = fmaf(w1, v1.y, ay);
        ax = fmaf(w2, v2.x, ax); ay = fmaf(w2, v2.y, ay);
        ax = fmaf(w3, v3.x, ax); ay = fmaf(w3, v3.y, ay);
    }
    for (; e < end; e++) {
        int j = g_col[e]; float w = g_wv[e];
        float2 v = __half22float2(ug[j*32+lane]);
        ax = fmaf(w, v.x, ax); ay = fmaf(w, v.y, ay);
    }

    const float2 x0v = reinterpret_cast<const float2*>(g_x0)[rbase];
    const float  s   = g_s[wid];
    float2* acc2 = reinterpret_cast<float2*>(g_acc);
    float2* z2   = reinterpret_cast<float2*>(g_buf0);
    __half2* unh = pick_h(unid);

    if (MODE == 0) {
        float2 zv = z2[rbase];                      // own u == z (exact)
        float kx = fmaf(s, ax - zv.x, x0v.x);
        float ky = fmaf(s, ay - zv.y, x0v.y);
        acc2[rbase] = make_float2(fmaf(cA, kx, zv.x), fmaf(cA, ky, zv.y));
        unh [rbase] = __floats2half2_rn(fmaf(cN, kx, zv.x), fmaf(cN, ky, zv.y));
    } else if (MODE == 1) {
        float2 uv = __half22float2(ug[rbase]);      // own u (fp16)
        float kx = fmaf(s, ax - uv.x, x0v.x);
        float ky = fmaf(s, ay - uv.y, x0v.y);
        float2 av = acc2[rbase];
        acc2[rbase] = make_float2(fmaf(cA, kx, av.x), fmaf(cA, ky, av.y));
        float2 zv = z2[rbase];
        unh [rbase] = __floats2half2_rn(fmaf(cN, kx, zv.x), fmaf(cN, ky, zv.y));
    } else {
        float2 uv = __half22float2(ug[rbase]);      // own u (fp16)
        float kx = fmaf(s, ax - uv.x, x0v.x);
        float ky = fmaf(s, ay - uv.y, x0v.y);
        float2 av = acc2[rbase];
        float zx = fmaf(cA, kx, av.x), zy = fmaf(cA, ky, av.y);
        z2[rbase]  = make_float2(zx, zy);           // new z (fp32 master)
        unh[rbase] = __floats2half2_rn(zx, zy);     // fp16 shadow for next step
    }
}

// ---------------- classifier: out = relu(z) @ m2_w + m2_b --------------------
__global__ __launch_bounds__(256) void classifier_kernel(
    const float* __restrict__ W, const float* __restrict__ bias,
    float* __restrict__ out)
{
    __shared__ float ws[HH * CC];
    __shared__ float bs[CC];
    const int t = threadIdx.x;
    #pragma unroll
    for (int i = 0; i < 10; i++) ws[t + i * 256] = W[t + i * 256];
    if (t < CC) bs[t] = bias[t];
    __syncthreads();
    int gid = blockIdx.x * 256 + t;
    if (gid >= NN * CC) return;
    int node = gid / CC, c = gid % CC;
    const float* zr = g_buf0 + node * HH;
    float acc = bs[c];
    #pragma unroll
    for (int k = 0; k < HH; k++) {
        float zv = fmaxf(__ldg(zr + k), 0.f);
        acc = fmaf(zv, ws[k * CC + c], acc);
    }
    out[gid] = acc;
}

// ---------------- launch ----------------
extern "C" void kernel_launch(void* const* d_in, const int* in_sizes, int n_in,
                              void* d_out, int out_size)
{
    const float* x    = (const float*)d_in[0];
    const float* ew   = (const float*)d_in[1];
    const float* m1w  = (const float*)d_in[2];
    const float* m1b  = (const float*)d_in[3];
    const float* alph = (const float*)d_in[4];
    const float* m2w  = (const float*)d_in[5];
    const float* m2b  = (const float*)d_in[6];
    const int*   esrc = (const int*)d_in[7];
    const int*   edst = (const int*)d_in[8];
    float* out = (float*)d_out;

    const float dt = 1.0f / 4.0f;

    // encoder + sigmoid/zero
    encoder_gemm<<<(NN + BM - 1) / BM, 256>>>(x, m1w, m1b);
    sigmoid_zero_kernel<<<(NN + 255) / 256, 256>>>(alph);

    // CSR build (counting sort by src)
    hist_kernel<<<(EE + 255) / 256, 256>>>(esrc);
    const int nb = (NN + 1023) / 1024;
    scan_block_kernel<<<nb, 1024>>>();
    scan_tops_kernel<<<1, 32>>>(nb);
    scan_add_kernel<<<nb, 1024>>>();
    scatter_kernel<<<(EE + 255) / 256, 256>>>(esrc, edst, ew);

    // RK4: 4 steps x 4 stages (warp per node, fp16 gathers)
    const int sgrid = (NN * 32 + 255) / 256;
    for (int step = 0; step < 4; step++) {
        stage_kernel<0><<<sgrid, 256>>>(0, 1, dt / 6.f, dt * 0.5f);  // gather zh  -> u1h
        stage_kernel<1><<<sgrid, 256>>>(1, 2, dt / 3.f, dt * 0.5f);  // gather u1h -> u2h
        stage_kernel<1><<<sgrid, 256>>>(2, 1, dt / 3.f, dt);         // gather u2h -> u1h
        stage_kernel<2><<<sgrid, 256>>>(1, 0, dt / 6.f, 0.f);        // gather u1h -> z, zh
    }

    // classifier
    classifier_kernel<<<(NN * CC + 255) / 256, 256>>>(m2w, m2b, out);
}